// round 11
// baseline (speedup 1.0000x reference)
#include <cuda_runtime.h>
#include <cstdint>

// Window attention via warp-level mma.sync (tf32), sm_103 (no 'a' features).
// B=8, C=512, H=W=128, heads=8, ws=8, hd=64 -> 16384 windows of 64 tok x 64 d.
// One CTA per window, 128 threads (4 warps). Warp w computes S/O rows 16w..16w+15.

#define STR 68   // smem row stride in floats: 68*4B -> row coefficient 4 mod 32 banks

__device__ __forceinline__ float tf32r(float x) {
    uint32_t u;
    asm("cvt.rna.tf32.f32 %0, %1;" : "=r"(u) : "f"(x));
    return __uint_as_float(u);
}

__device__ __forceinline__ void mma8(float c[4],
                                     uint32_t a0, uint32_t a1, uint32_t a2, uint32_t a3,
                                     uint32_t b0, uint32_t b1) {
    asm volatile(
        "mma.sync.aligned.m16n8k8.row.col.f32.tf32.tf32.f32 "
        "{%0,%1,%2,%3}, {%4,%5,%6,%7}, {%8,%9}, {%0,%1,%2,%3};"
        : "+f"(c[0]), "+f"(c[1]), "+f"(c[2]), "+f"(c[3])
        : "r"(a0), "r"(a1), "r"(a2), "r"(a3), "r"(b0), "r"(b1));
}

__device__ __forceinline__ uint32_t fbits(float x) { return __float_as_uint(x); }

__global__ __launch_bounds__(128, 4)
void win_attn_mma(const float* __restrict__ q,
                  const float* __restrict__ k,
                  const float* __restrict__ v,
                  float* __restrict__ out)
{
    extern __shared__ float smem[];
    float* qs = smem;             // Q [tok][d] (tf32-rounded); later O staging [d][tok]
    float* ks = smem + 64 * STR;  // K [tok][d] (tf32); later P [ti][tj] (tf32)
    float* vs = smem + 128 * STR; // V transposed [d][tok] (tf32)

    const int tid  = threadIdx.x;
    const int lane = tid & 31;
    const int wid  = tid >> 5;

    const int win = blockIdx.x;
    const int wx  = win & 15;
    const int wy  = (win >> 4) & 15;
    const int bh  = win >> 8;
    const size_t base = (size_t)bh * 1048576 + (size_t)(wy * 8) * 128 + (size_t)(wx * 8);

    // ---- load Q,K,V (coalesced float4 over x), round to tf32 at store ----
    #pragma unroll
    for (int it = 0; it < 8; it++) {
        int lin = it * 128 + tid;          // (d, y, x4)
        int x4  = (lin & 1) * 4;
        int y   = (lin >> 1) & 7;
        int d   = lin >> 4;
        size_t g = base + (size_t)d * 16384 + (size_t)y * 128 + x4;
        float4 qv = *(const float4*)(q + g);
        float4 kv = *(const float4*)(k + g);
        float4 vv = *(const float4*)(v + g);
        int t0 = y * 8 + x4;
        float qa[4] = {qv.x, qv.y, qv.z, qv.w};
        float ka[4] = {kv.x, kv.y, kv.z, kv.w};
        #pragma unroll
        for (int e = 0; e < 4; e++) {
            qs[(t0 + e) * STR + d] = tf32r(qa[e]);
            ks[(t0 + e) * STR + d] = tf32r(ka[e]);
        }
        float4 vr = make_float4(tf32r(vv.x), tf32r(vv.y), tf32r(vv.z), tf32r(vv.w));
        *(float4*)&vs[d * STR + t0] = vr;  // transposed: [d][tok], 16B aligned
    }
    __syncthreads();

    const int i0 = wid * 16;
    const int r  = lane >> 2;   // fragment row within tile
    const int cq = lane & 3;    // fragment col (k) within tile

    // ---- GEMM1: S[16,64] = Q[i0..][.] K^T, acc in registers ----
    float acc[8][4];
    #pragma unroll
    for (int nt = 0; nt < 8; nt++)
        #pragma unroll
        for (int e = 0; e < 4; e++) acc[nt][e] = 0.f;

    #pragma unroll
    for (int kt = 0; kt < 8; kt++) {
        int k0 = kt * 8;
        uint32_t a0 = fbits(qs[(i0 + r) * STR + k0 + cq]);
        uint32_t a1 = fbits(qs[(i0 + r + 8) * STR + k0 + cq]);
        uint32_t a2 = fbits(qs[(i0 + r) * STR + k0 + cq + 4]);
        uint32_t a3 = fbits(qs[(i0 + r + 8) * STR + k0 + cq + 4]);
        #pragma unroll
        for (int nt = 0; nt < 8; nt++) {
            int n0 = nt * 8;
            uint32_t b0 = fbits(ks[(n0 + r) * STR + k0 + cq]);      // B[k][n]=K[n][k]
            uint32_t b1 = fbits(ks[(n0 + r) * STR + k0 + cq + 4]);
            mma8(acc[nt], a0, a1, a2, a3, b0, b1);
        }
    }
    __syncthreads();   // all warps done reading ks before P overlays it

    // ---- softmax in registers: rows rA=i0+r and rB=rA+8 ----
    // thread holds acc[nt][0..1] on row rA (cols 8nt+2cq+{0,1}), acc[nt][2..3] on rB
    float mA = -1e30f, mB = -1e30f;
    #pragma unroll
    for (int nt = 0; nt < 8; nt++) {
        mA = fmaxf(mA, fmaxf(acc[nt][0], acc[nt][1]));
        mB = fmaxf(mB, fmaxf(acc[nt][2], acc[nt][3]));
    }
    mA = fmaxf(mA, __shfl_xor_sync(0xffffffffu, mA, 1));
    mA = fmaxf(mA, __shfl_xor_sync(0xffffffffu, mA, 2));
    mB = fmaxf(mB, __shfl_xor_sync(0xffffffffu, mB, 1));
    mB = fmaxf(mB, __shfl_xor_sync(0xffffffffu, mB, 2));

    float sA = 0.f, sB = 0.f;
    #pragma unroll
    for (int nt = 0; nt < 8; nt++) {
        acc[nt][0] = __expf((acc[nt][0] - mA) * 0.125f); sA += acc[nt][0];
        acc[nt][1] = __expf((acc[nt][1] - mA) * 0.125f); sA += acc[nt][1];
        acc[nt][2] = __expf((acc[nt][2] - mB) * 0.125f); sB += acc[nt][2];
        acc[nt][3] = __expf((acc[nt][3] - mB) * 0.125f); sB += acc[nt][3];
    }
    sA += __shfl_xor_sync(0xffffffffu, sA, 1);
    sA += __shfl_xor_sync(0xffffffffu, sA, 2);
    sB += __shfl_xor_sync(0xffffffffu, sB, 1);
    sB += __shfl_xor_sync(0xffffffffu, sB, 2);
    float invA = __fdividef(1.f, sA);
    float invB = __fdividef(1.f, sB);

    // ---- write P (tf32-rounded) over ks ----
    float* ps = ks;
    const int rA = i0 + r;
    #pragma unroll
    for (int nt = 0; nt < 8; nt++) {
        int c0 = nt * 8 + 2 * cq;
        ps[rA * STR + c0]           = tf32r(acc[nt][0] * invA);
        ps[rA * STR + c0 + 1]       = tf32r(acc[nt][1] * invA);
        ps[(rA + 8) * STR + c0]     = tf32r(acc[nt][2] * invB);
        ps[(rA + 8) * STR + c0 + 1] = tf32r(acc[nt][3] * invB);
    }
    __syncthreads();

    // ---- GEMM2: O[16,64] = P . V   (B[k][n] = V[tok=k][d=n] = vs[n][k]) ----
    #pragma unroll
    for (int nt = 0; nt < 8; nt++)
        #pragma unroll
        for (int e = 0; e < 4; e++) acc[nt][e] = 0.f;

    #pragma unroll
    for (int kt = 0; kt < 8; kt++) {
        int k0 = kt * 8;
        uint32_t a0 = fbits(ps[(i0 + r) * STR + k0 + cq]);
        uint32_t a1 = fbits(ps[(i0 + r + 8) * STR + k0 + cq]);
        uint32_t a2 = fbits(ps[(i0 + r) * STR + k0 + cq + 4]);
        uint32_t a3 = fbits(ps[(i0 + r + 8) * STR + k0 + cq + 4]);
        #pragma unroll
        for (int nt = 0; nt < 8; nt++) {
            int n0 = nt * 8;
            uint32_t b0 = fbits(vs[(n0 + r) * STR + k0 + cq]);
            uint32_t b1 = fbits(vs[(n0 + r) * STR + k0 + cq + 4]);
            mma8(acc[nt], a0, a1, a2, a3, b0, b1);
        }
    }
    __syncthreads();   // all warps done reading qs(GEMM1)/vs before staging overlays qs

    // ---- stage O into qs as [d][tok] (conflict-free STS), then coalesced STG ----
    float* os = qs;
    #pragma unroll
    for (int nt = 0; nt < 8; nt++) {
        int c0 = nt * 8 + 2 * cq;
        os[c0 * STR + rA]           = acc[nt][0];
        os[(c0 + 1) * STR + rA]     = acc[nt][1];
        os[c0 * STR + rA + 8]       = acc[nt][2];
        os[(c0 + 1) * STR + rA + 8] = acc[nt][3];
    }
    __syncthreads();

    #pragma unroll
    for (int it = 0; it < 8; it++) {
        int lin = it * 128 + tid;
        int x4  = (lin & 1) * 4;
        int y   = (lin >> 1) & 7;
        int d   = lin >> 4;
        int t0  = y * 8 + x4;
        float4 o4 = *(const float4*)&os[d * STR + t0];
        *(float4*)(out + base + (size_t)d * 16384 + (size_t)y * 128 + x4) = o4;
    }
}

extern "C" void kernel_launch(void* const* d_in, const int* in_sizes, int n_in,
                              void* d_out, int out_size)
{
    (void)in_sizes; (void)n_in; (void)out_size;
    const float* q = (const float*)d_in[0];
    const float* k = (const float*)d_in[1];
    const float* v = (const float*)d_in[2];
    float* out = (float*)d_out;

    const int smem_bytes = 3 * 64 * STR * sizeof(float);  // 52224
    cudaFuncSetAttribute(win_attn_mma,
                         cudaFuncAttributeMaxDynamicSharedMemorySize, smem_bytes);
    win_attn_mma<<<16384, 128, smem_bytes>>>(q, k, v, out);
}

// round 12
// speedup vs baseline: 1.0008x; 1.0008x over previous
#include <cuda_runtime.h>
#include <cstdint>

// Window attention via warp-level mma.sync (tf32), sm_103 (no 'a' features).
// B=8, C=512, H=W=128, heads=8, ws=8, hd=64 -> 16384 windows of 64 tok x 64 d.
// One CTA per window, 128 threads (4 warps). Warp w computes S/O rows 16w..16w+15.

#define STR 68   // smem row stride in floats: 68*4B -> row coefficient 4 mod 32 banks

__device__ __forceinline__ float tf32r(float x) {
    uint32_t u;
    asm("cvt.rna.tf32.f32 %0, %1;" : "=r"(u) : "f"(x));
    return __uint_as_float(u);
}

__device__ __forceinline__ void mma8(float c[4],
                                     uint32_t a0, uint32_t a1, uint32_t a2, uint32_t a3,
                                     uint32_t b0, uint32_t b1) {
    asm volatile(
        "mma.sync.aligned.m16n8k8.row.col.f32.tf32.tf32.f32 "
        "{%0,%1,%2,%3}, {%4,%5,%6,%7}, {%8,%9}, {%0,%1,%2,%3};"
        : "+f"(c[0]), "+f"(c[1]), "+f"(c[2]), "+f"(c[3])
        : "r"(a0), "r"(a1), "r"(a2), "r"(a3), "r"(b0), "r"(b1));
}

__device__ __forceinline__ uint32_t fbits(float x) { return __float_as_uint(x); }

__global__ __launch_bounds__(128, 4)
void win_attn_mma(const float* __restrict__ q,
                  const float* __restrict__ k,
                  const float* __restrict__ v,
                  float* __restrict__ out)
{
    extern __shared__ float smem[];
    float* qs = smem;             // Q [tok][d] (tf32-rounded); later O staging [d][tok]
    float* ks = smem + 64 * STR;  // K [tok][d] (tf32); later P [ti][tj] (tf32)
    float* vs = smem + 128 * STR; // V transposed [d][tok] (tf32)

    const int tid  = threadIdx.x;
    const int lane = tid & 31;
    const int wid  = tid >> 5;

    const int win = blockIdx.x;
    const int wx  = win & 15;
    const int wy  = (win >> 4) & 15;
    const int bh  = win >> 8;
    const size_t base = (size_t)bh * 1048576 + (size_t)(wy * 8) * 128 + (size_t)(wx * 8);

    // ---- load Q,K,V (coalesced float4 over x), round to tf32 at store ----
    #pragma unroll
    for (int it = 0; it < 8; it++) {
        int lin = it * 128 + tid;          // (d, y, x4)
        int x4  = (lin & 1) * 4;
        int y   = (lin >> 1) & 7;
        int d   = lin >> 4;
        size_t g = base + (size_t)d * 16384 + (size_t)y * 128 + x4;
        float4 qv = *(const float4*)(q + g);
        float4 kv = *(const float4*)(k + g);
        float4 vv = *(const float4*)(v + g);
        int t0 = y * 8 + x4;
        float qa[4] = {qv.x, qv.y, qv.z, qv.w};
        float ka[4] = {kv.x, kv.y, kv.z, kv.w};
        #pragma unroll
        for (int e = 0; e < 4; e++) {
            qs[(t0 + e) * STR + d] = tf32r(qa[e]);
            ks[(t0 + e) * STR + d] = tf32r(ka[e]);
        }
        float4 vr = make_float4(tf32r(vv.x), tf32r(vv.y), tf32r(vv.z), tf32r(vv.w));
        *(float4*)&vs[d * STR + t0] = vr;  // transposed: [d][tok], 16B aligned
    }
    __syncthreads();

    const int i0 = wid * 16;
    const int r  = lane >> 2;   // fragment row within tile
    const int cq = lane & 3;    // fragment col (k) within tile

    // ---- GEMM1: S[16,64] = Q[i0..][.] K^T, acc in registers ----
    float acc[8][4];
    #pragma unroll
    for (int nt = 0; nt < 8; nt++)
        #pragma unroll
        for (int e = 0; e < 4; e++) acc[nt][e] = 0.f;

    #pragma unroll
    for (int kt = 0; kt < 8; kt++) {
        int k0 = kt * 8;
        uint32_t a0 = fbits(qs[(i0 + r) * STR + k0 + cq]);
        uint32_t a1 = fbits(qs[(i0 + r + 8) * STR + k0 + cq]);
        uint32_t a2 = fbits(qs[(i0 + r) * STR + k0 + cq + 4]);
        uint32_t a3 = fbits(qs[(i0 + r + 8) * STR + k0 + cq + 4]);
        #pragma unroll
        for (int nt = 0; nt < 8; nt++) {
            int n0 = nt * 8;
            uint32_t b0 = fbits(ks[(n0 + r) * STR + k0 + cq]);      // B[k][n]=K[n][k]
            uint32_t b1 = fbits(ks[(n0 + r) * STR + k0 + cq + 4]);
            mma8(acc[nt], a0, a1, a2, a3, b0, b1);
        }
    }
    __syncthreads();   // all warps done reading ks before P overlays it

    // ---- softmax in registers: rows rA=i0+r and rB=rA+8 ----
    // thread holds acc[nt][0..1] on row rA (cols 8nt+2cq+{0,1}), acc[nt][2..3] on rB
    float mA = -1e30f, mB = -1e30f;
    #pragma unroll
    for (int nt = 0; nt < 8; nt++) {
        mA = fmaxf(mA, fmaxf(acc[nt][0], acc[nt][1]));
        mB = fmaxf(mB, fmaxf(acc[nt][2], acc[nt][3]));
    }
    mA = fmaxf(mA, __shfl_xor_sync(0xffffffffu, mA, 1));
    mA = fmaxf(mA, __shfl_xor_sync(0xffffffffu, mA, 2));
    mB = fmaxf(mB, __shfl_xor_sync(0xffffffffu, mB, 1));
    mB = fmaxf(mB, __shfl_xor_sync(0xffffffffu, mB, 2));

    float sA = 0.f, sB = 0.f;
    #pragma unroll
    for (int nt = 0; nt < 8; nt++) {
        acc[nt][0] = __expf((acc[nt][0] - mA) * 0.125f); sA += acc[nt][0];
        acc[nt][1] = __expf((acc[nt][1] - mA) * 0.125f); sA += acc[nt][1];
        acc[nt][2] = __expf((acc[nt][2] - mB) * 0.125f); sB += acc[nt][2];
        acc[nt][3] = __expf((acc[nt][3] - mB) * 0.125f); sB += acc[nt][3];
    }
    sA += __shfl_xor_sync(0xffffffffu, sA, 1);
    sA += __shfl_xor_sync(0xffffffffu, sA, 2);
    sB += __shfl_xor_sync(0xffffffffu, sB, 1);
    sB += __shfl_xor_sync(0xffffffffu, sB, 2);
    float invA = __fdividef(1.f, sA);
    float invB = __fdividef(1.f, sB);

    // ---- write P (tf32-rounded) over ks ----
    float* ps = ks;
    const int rA = i0 + r;
    #pragma unroll
    for (int nt = 0; nt < 8; nt++) {
        int c0 = nt * 8 + 2 * cq;
        ps[rA * STR + c0]           = tf32r(acc[nt][0] * invA);
        ps[rA * STR + c0 + 1]       = tf32r(acc[nt][1] * invA);
        ps[(rA + 8) * STR + c0]     = tf32r(acc[nt][2] * invB);
        ps[(rA + 8) * STR + c0 + 1] = tf32r(acc[nt][3] * invB);
    }
    __syncthreads();

    // ---- GEMM2: O[16,64] = P . V   (B[k][n] = V[tok=k][d=n] = vs[n][k]) ----
    #pragma unroll
    for (int nt = 0; nt < 8; nt++)
        #pragma unroll
        for (int e = 0; e < 4; e++) acc[nt][e] = 0.f;

    #pragma unroll
    for (int kt = 0; kt < 8; kt++) {
        int k0 = kt * 8;
        uint32_t a0 = fbits(ps[(i0 + r) * STR + k0 + cq]);
        uint32_t a1 = fbits(ps[(i0 + r + 8) * STR + k0 + cq]);
        uint32_t a2 = fbits(ps[(i0 + r) * STR + k0 + cq + 4]);
        uint32_t a3 = fbits(ps[(i0 + r + 8) * STR + k0 + cq + 4]);
        #pragma unroll
        for (int nt = 0; nt < 8; nt++) {
            int n0 = nt * 8;
            uint32_t b0 = fbits(vs[(n0 + r) * STR + k0 + cq]);
            uint32_t b1 = fbits(vs[(n0 + r) * STR + k0 + cq + 4]);
            mma8(acc[nt], a0, a1, a2, a3, b0, b1);
        }
    }
    __syncthreads();   // all warps done reading qs(GEMM1)/vs before staging overlays qs

    // ---- stage O into qs as [d][tok] (conflict-free STS), then coalesced STG ----
    float* os = qs;
    #pragma unroll
    for (int nt = 0; nt < 8; nt++) {
        int c0 = nt * 8 + 2 * cq;
        os[c0 * STR + rA]           = acc[nt][0];
        os[(c0 + 1) * STR + rA]     = acc[nt][1];
        os[c0 * STR + rA + 8]       = acc[nt][2];
        os[(c0 + 1) * STR + rA + 8] = acc[nt][3];
    }
    __syncthreads();

    #pragma unroll
    for (int it = 0; it < 8; it++) {
        int lin = it * 128 + tid;
        int x4  = (lin & 1) * 4;
        int y   = (lin >> 1) & 7;
        int d   = lin >> 4;
        int t0  = y * 8 + x4;
        float4 o4 = *(const float4*)&os[d * STR + t0];
        *(float4*)(out + base + (size_t)d * 16384 + (size_t)y * 128 + x4) = o4;
    }
}

extern "C" void kernel_launch(void* const* d_in, const int* in_sizes, int n_in,
                              void* d_out, int out_size)
{
    (void)in_sizes; (void)n_in; (void)out_size;
    const float* q = (const float*)d_in[0];
    const float* k = (const float*)d_in[1];
    const float* v = (const float*)d_in[2];
    float* out = (float*)d_out;

    const int smem_bytes = 3 * 64 * STR * sizeof(float);  // 52224
    cudaFuncSetAttribute(win_attn_mma,
                         cudaFuncAttributeMaxDynamicSharedMemorySize, smem_bytes);
    win_attn_mma<<<16384, 128, smem_bytes>>>(q, k, v, out);
}

// round 13
// speedup vs baseline: 1.0035x; 1.0027x over previous
#include <cuda_runtime.h>
#include <cstdint>

// Window attention via warp-level mma.sync (tf32), sm_103 (no 'a' features).
// B=8, C=512, H=W=128, heads=8, ws=8, hd=64 -> 16384 windows of 64 tok x 64 d.
// One CTA per window, 128 threads (4 warps). Warp w computes S/O rows 16w..16w+15.

#define STR 68   // smem row stride in floats: 68*4B -> row coefficient 4 mod 32 banks

__device__ __forceinline__ float tf32r(float x) {
    uint32_t u;
    asm("cvt.rna.tf32.f32 %0, %1;" : "=r"(u) : "f"(x));
    return __uint_as_float(u);
}

__device__ __forceinline__ void mma8(float c[4],
                                     uint32_t a0, uint32_t a1, uint32_t a2, uint32_t a3,
                                     uint32_t b0, uint32_t b1) {
    asm volatile(
        "mma.sync.aligned.m16n8k8.row.col.f32.tf32.tf32.f32 "
        "{%0,%1,%2,%3}, {%4,%5,%6,%7}, {%8,%9}, {%0,%1,%2,%3};"
        : "+f"(c[0]), "+f"(c[1]), "+f"(c[2]), "+f"(c[3])
        : "r"(a0), "r"(a1), "r"(a2), "r"(a3), "r"(b0), "r"(b1));
}

__device__ __forceinline__ uint32_t fbits(float x) { return __float_as_uint(x); }

__global__ __launch_bounds__(128, 4)
void win_attn_mma(const float* __restrict__ q,
                  const float* __restrict__ k,
                  const float* __restrict__ v,
                  float* __restrict__ out)
{
    extern __shared__ float smem[];
    float* qs = smem;             // Q [tok][d] (tf32-rounded); later O staging [d][tok]
    float* ks = smem + 64 * STR;  // K [tok][d] (tf32); later P [ti][tj] (tf32)
    float* vs = smem + 128 * STR; // V transposed [d][tok] (tf32)

    const int tid  = threadIdx.x;
    const int lane = tid & 31;
    const int wid  = tid >> 5;

    const int win = blockIdx.x;
    const int wx  = win & 15;
    const int wy  = (win >> 4) & 15;
    const int bh  = win >> 8;
    const size_t base = (size_t)bh * 1048576 + (size_t)(wy * 8) * 128 + (size_t)(wx * 8);

    // ---- load Q,K,V (coalesced float4 over x), round to tf32 at store ----
    #pragma unroll
    for (int it = 0; it < 8; it++) {
        int lin = it * 128 + tid;          // (d, y, x4)
        int x4  = (lin & 1) * 4;
        int y   = (lin >> 1) & 7;
        int d   = lin >> 4;
        size_t g = base + (size_t)d * 16384 + (size_t)y * 128 + x4;
        float4 qv = *(const float4*)(q + g);
        float4 kv = *(const float4*)(k + g);
        float4 vv = *(const float4*)(v + g);
        int t0 = y * 8 + x4;
        float qa[4] = {qv.x, qv.y, qv.z, qv.w};
        float ka[4] = {kv.x, kv.y, kv.z, kv.w};
        #pragma unroll
        for (int e = 0; e < 4; e++) {
            qs[(t0 + e) * STR + d] = tf32r(qa[e]);
            ks[(t0 + e) * STR + d] = tf32r(ka[e]);
        }
        float4 vr = make_float4(tf32r(vv.x), tf32r(vv.y), tf32r(vv.z), tf32r(vv.w));
        *(float4*)&vs[d * STR + t0] = vr;  // transposed: [d][tok], 16B aligned
    }
    __syncthreads();

    const int i0 = wid * 16;
    const int r  = lane >> 2;   // fragment row within tile
    const int cq = lane & 3;    // fragment col (k) within tile

    // ---- GEMM1: S[16,64] = Q[i0..][.] K^T, acc in registers ----
    float acc[8][4];
    #pragma unroll
    for (int nt = 0; nt < 8; nt++)
        #pragma unroll
        for (int e = 0; e < 4; e++) acc[nt][e] = 0.f;

    #pragma unroll
    for (int kt = 0; kt < 8; kt++) {
        int k0 = kt * 8;
        uint32_t a0 = fbits(qs[(i0 + r) * STR + k0 + cq]);
        uint32_t a1 = fbits(qs[(i0 + r + 8) * STR + k0 + cq]);
        uint32_t a2 = fbits(qs[(i0 + r) * STR + k0 + cq + 4]);
        uint32_t a3 = fbits(qs[(i0 + r + 8) * STR + k0 + cq + 4]);
        #pragma unroll
        for (int nt = 0; nt < 8; nt++) {
            int n0 = nt * 8;
            uint32_t b0 = fbits(ks[(n0 + r) * STR + k0 + cq]);      // B[k][n]=K[n][k]
            uint32_t b1 = fbits(ks[(n0 + r) * STR + k0 + cq + 4]);
            mma8(acc[nt], a0, a1, a2, a3, b0, b1);
        }
    }
    __syncthreads();   // all warps done reading ks before P overlays it

    // ---- softmax in registers: rows rA=i0+r and rB=rA+8 ----
    // thread holds acc[nt][0..1] on row rA (cols 8nt+2cq+{0,1}), acc[nt][2..3] on rB
    float mA = -1e30f, mB = -1e30f;
    #pragma unroll
    for (int nt = 0; nt < 8; nt++) {
        mA = fmaxf(mA, fmaxf(acc[nt][0], acc[nt][1]));
        mB = fmaxf(mB, fmaxf(acc[nt][2], acc[nt][3]));
    }
    mA = fmaxf(mA, __shfl_xor_sync(0xffffffffu, mA, 1));
    mA = fmaxf(mA, __shfl_xor_sync(0xffffffffu, mA, 2));
    mB = fmaxf(mB, __shfl_xor_sync(0xffffffffu, mB, 1));
    mB = fmaxf(mB, __shfl_xor_sync(0xffffffffu, mB, 2));

    float sA = 0.f, sB = 0.f;
    #pragma unroll
    for (int nt = 0; nt < 8; nt++) {
        acc[nt][0] = __expf((acc[nt][0] - mA) * 0.125f); sA += acc[nt][0];
        acc[nt][1] = __expf((acc[nt][1] - mA) * 0.125f); sA += acc[nt][1];
        acc[nt][2] = __expf((acc[nt][2] - mB) * 0.125f); sB += acc[nt][2];
        acc[nt][3] = __expf((acc[nt][3] - mB) * 0.125f); sB += acc[nt][3];
    }
    sA += __shfl_xor_sync(0xffffffffu, sA, 1);
    sA += __shfl_xor_sync(0xffffffffu, sA, 2);
    sB += __shfl_xor_sync(0xffffffffu, sB, 1);
    sB += __shfl_xor_sync(0xffffffffu, sB, 2);
    float invA = __fdividef(1.f, sA);
    float invB = __fdividef(1.f, sB);

    // ---- write P (tf32-rounded) over ks ----
    float* ps = ks;
    const int rA = i0 + r;
    #pragma unroll
    for (int nt = 0; nt < 8; nt++) {
        int c0 = nt * 8 + 2 * cq;
        ps[rA * STR + c0]           = tf32r(acc[nt][0] * invA);
        ps[rA * STR + c0 + 1]       = tf32r(acc[nt][1] * invA);
        ps[(rA + 8) * STR + c0]     = tf32r(acc[nt][2] * invB);
        ps[(rA + 8) * STR + c0 + 1] = tf32r(acc[nt][3] * invB);
    }
    __syncthreads();

    // ---- GEMM2: O[16,64] = P . V   (B[k][n] = V[tok=k][d=n] = vs[n][k]) ----
    #pragma unroll
    for (int nt = 0; nt < 8; nt++)
        #pragma unroll
        for (int e = 0; e < 4; e++) acc[nt][e] = 0.f;

    #pragma unroll
    for (int kt = 0; kt < 8; kt++) {
        int k0 = kt * 8;
        uint32_t a0 = fbits(ps[(i0 + r) * STR + k0 + cq]);
        uint32_t a1 = fbits(ps[(i0 + r + 8) * STR + k0 + cq]);
        uint32_t a2 = fbits(ps[(i0 + r) * STR + k0 + cq + 4]);
        uint32_t a3 = fbits(ps[(i0 + r + 8) * STR + k0 + cq + 4]);
        #pragma unroll
        for (int nt = 0; nt < 8; nt++) {
            int n0 = nt * 8;
            uint32_t b0 = fbits(vs[(n0 + r) * STR + k0 + cq]);
            uint32_t b1 = fbits(vs[(n0 + r) * STR + k0 + cq + 4]);
            mma8(acc[nt], a0, a1, a2, a3, b0, b1);
        }
    }
    __syncthreads();   // all warps done reading qs(GEMM1)/vs before staging overlays qs

    // ---- stage O into qs as [d][tok] (conflict-free STS), then coalesced STG ----
    float* os = qs;
    #pragma unroll
    for (int nt = 0; nt < 8; nt++) {
        int c0 = nt * 8 + 2 * cq;
        os[c0 * STR + rA]           = acc[nt][0];
        os[(c0 + 1) * STR + rA]     = acc[nt][1];
        os[c0 * STR + rA + 8]       = acc[nt][2];
        os[(c0 + 1) * STR + rA + 8] = acc[nt][3];
    }
    __syncthreads();

    #pragma unroll
    for (int it = 0; it < 8; it++) {
        int lin = it * 128 + tid;
        int x4  = (lin & 1) * 4;
        int y   = (lin >> 1) & 7;
        int d   = lin >> 4;
        int t0  = y * 8 + x4;
        float4 o4 = *(const float4*)&os[d * STR + t0];
        *(float4*)(out + base + (size_t)d * 16384 + (size_t)y * 128 + x4) = o4;
    }
}

extern "C" void kernel_launch(void* const* d_in, const int* in_sizes, int n_in,
                              void* d_out, int out_size)
{
    (void)in_sizes; (void)n_in; (void)out_size;
    const float* q = (const float*)d_in[0];
    const float* k = (const float*)d_in[1];
    const float* v = (const float*)d_in[2];
    float* out = (float*)d_out;

    const int smem_bytes = 3 * 64 * STR * sizeof(float);  // 52224
    cudaFuncSetAttribute(win_attn_mma,
                         cudaFuncAttributeMaxDynamicSharedMemorySize, smem_bytes);
    win_attn_mma<<<16384, 128, smem_bytes>>>(q, k, v, out);
}